// round 1
// baseline (speedup 1.0000x reference)
#include <cuda_runtime.h>

// Problem constants
#define BB 2
#define HH 16
#define SS 2048
#define DD 64
#define QT 16          // query rows per CTA
#define KT 128         // key/value rows per SMEM block
#define NTH 256
#define KPITCH 66      // K tile row pitch (floats): conflict-free LDS.64 k-frags

#define SMEM_Q    0                       // QT*DD        = 1024 floats
#define SMEM_SC   (QT*DD)                 // QT*SS        = 32768 floats
#define SMEM_KV   (QT*DD + QT*SS)         // KT*KPITCH    = 8448 floats
#define SMEM_FLOATS (QT*DD + QT*SS + KT*KPITCH)
#define SMEM_BYTES  (SMEM_FLOATS * 4)     // 168960 B

typedef unsigned long long ull;

__device__ __forceinline__ ull fma2(ull a, ull b, ull c) {
    ull d;
    asm("fma.rn.f32x2 %0, %1, %2, %3;" : "=l"(d) : "l"(a), "l"(b), "l"(c));
    return d;
}
__device__ __forceinline__ ull pk2(float x, float y) {
    ull r;
    asm("mov.b64 %0, {%1, %2};" : "=l"(r) : "f"(x), "f"(y));
    return r;
}
__device__ __forceinline__ float2 upk2(ull v) {
    float2 f;
    asm("mov.b64 {%0, %1}, %2;" : "=f"(f.x), "=f"(f.y) : "l"(v));
    return f;
}

__global__ void __launch_bounds__(NTH, 1)
sdpa_fused_kernel(const float* __restrict__ Q, const float* __restrict__ K,
                  const float* __restrict__ V, const int* __restrict__ Mask,
                  float* __restrict__ Out, float* __restrict__ Prob) {
    extern __shared__ float smem[];
    float* q_s = smem + SMEM_Q;
    float* sc  = smem + SMEM_SC;
    float* kv  = smem + SMEM_KV;

    const int t    = threadIdx.x;
    const int bid  = blockIdx.x;
    const int bh   = bid >> 7;          // / (SS/QT) = 128 q-tiles per (b,h)
    const int qblk = bid & 127;
    const int q0   = qblk * QT;

    const float* Qp = Q + ((size_t)bh * SS + q0) * DD;
    const float* Kp = K + (size_t)bh * SS * DD;
    const float* Vp = V + (size_t)bh * SS * DD;

    // ---- Load Q tile (16x64 = 1024 floats, contiguous) ----
    ((float4*)q_s)[t] = ((const float4*)Qp)[t];

    // ================= Phase 1: S = QK^T (masked, scaled) =================
    // Thread micro-tile: 4 q-rows x 2 keys.  qg = t>>6 (4 groups of 4q),
    // kg2 = (t&63)*2 (64 groups of 2k -> 128 keys per block).
    const int qb  = (t >> 6) * 4;
    const int kg2 = (t & 63) * 2;

    for (int kb = 0; kb < SS / KT; kb++) {
        __syncthreads();  // previous readers of kv done (and q_s ready on iter 0)
        // Load K block [128][64] -> kv pitched [128][66]
        #pragma unroll
        for (int j = 0; j < (KT * DD / 4) / NTH; j++) {
            int i  = t + j * NTH;
            int kk = i >> 4;
            int dq = i & 15;
            float4 f = *(const float4*)(Kp + (size_t)(kb * KT + kk) * DD + dq * 4);
            float* dst = kv + kk * KPITCH + dq * 4;
            *(float2*)(dst)     = make_float2(f.x, f.y);
            *(float2*)(dst + 2) = make_float2(f.z, f.w);
        }
        __syncthreads();

        ull acc[4][2];
        #pragma unroll
        for (int qq = 0; qq < 4; qq++) { acc[qq][0] = 0ull; acc[qq][1] = 0ull; }

        const float* krow0 = kv + (kg2 + 0) * KPITCH;
        const float* krow1 = kv + (kg2 + 1) * KPITCH;
        #pragma unroll
        for (int d = 0; d < DD; d += 2) {
            ull k0 = *(const ull*)(krow0 + d);
            ull k1 = *(const ull*)(krow1 + d);
            #pragma unroll
            for (int qq = 0; qq < 4; qq++) {
                ull qf = *(const ull*)(q_s + (qb + qq) * DD + d);
                acc[qq][0] = fma2(qf, k0, acc[qq][0]);
                acc[qq][1] = fma2(qf, k1, acc[qq][1]);
            }
        }

        const int kglob = kb * KT + kg2;
        #pragma unroll
        for (int qq = 0; qq < 4; qq++) {
            int qrow = qb + qq;
            float2 a0 = upk2(acc[qq][0]);
            float2 a1 = upk2(acc[qq][1]);
            float s0 = a0.x + a0.y;
            float s1 = a1.x + a1.y;
            int2 mm = *(const int2*)(Mask + (size_t)(q0 + qrow) * SS + kglob);
            float2 o;
            o.x = mm.x ? s0 * 0.125f : -1e30f;
            o.y = mm.y ? s1 * 0.125f : -1e30f;
            *(float2*)(sc + qrow * SS + kglob) = o;
        }
    }
    __syncthreads();

    // ================= Phase 2: row softmax + write score =================
    {
        const int w = t >> 5, l = t & 31;
        #pragma unroll
        for (int rr = 0; rr < 2; rr++) {
            int r = w * 2 + rr;
            float4* row = (float4*)(sc + r * SS);
            float m = -1e30f;
            #pragma unroll
            for (int i = 0; i < 16; i++) {
                float4 f = row[l + 32 * i];
                m = fmaxf(m, fmaxf(fmaxf(f.x, f.y), fmaxf(f.z, f.w)));
            }
            #pragma unroll
            for (int off = 16; off > 0; off >>= 1)
                m = fmaxf(m, __shfl_xor_sync(0xFFFFFFFFu, m, off));

            float sum = 0.f;
            #pragma unroll
            for (int i = 0; i < 16; i++) {
                float4 f = row[l + 32 * i];
                f.x = __expf(f.x - m); f.y = __expf(f.y - m);
                f.z = __expf(f.z - m); f.w = __expf(f.w - m);
                sum += (f.x + f.y) + (f.z + f.w);
                row[l + 32 * i] = f;
            }
            #pragma unroll
            for (int off = 16; off > 0; off >>= 1)
                sum += __shfl_xor_sync(0xFFFFFFFFu, sum, off);
            float inv = 1.f / sum;

            float4* grow = (float4*)(Prob + ((size_t)bh * SS + q0 + r) * SS);
            #pragma unroll
            for (int i = 0; i < 16; i++) {
                float4 f = row[l + 32 * i];
                f.x *= inv; f.y *= inv; f.z *= inv; f.w *= inv;
                row[l + 32 * i]  = f;   // normalized P for phase 3
                grow[l + 32 * i] = f;   // score output
            }
        }
    }

    // ================= Phase 3: O = P @ V =================
    // Thread micro-tile: 1 q-row x 4 d.  qg = t>>4 (16 q rows), dg = t&15.
    {
        const int dg = t & 15, qg = t >> 4;
        ull acc0 = 0ull, acc1 = 0ull;

        for (int kb = 0; kb < SS / KT; kb++) {
            __syncthreads();  // prev readers of kv done; on iter 0: P normalized
            #pragma unroll
            for (int j = 0; j < (KT * DD / 4) / NTH; j++) {
                int i = t + j * NTH;
                ((float4*)kv)[i] = ((const float4*)(Vp + (size_t)kb * KT * DD))[i];
            }
            __syncthreads();

            const float* prow = sc + qg * SS + kb * KT;
            #pragma unroll 8
            for (int kk = 0; kk < KT; kk += 2) {
                float2 pp = *(const float2*)(prow + kk);
                ull px = pk2(pp.x, pp.x);
                ull py = pk2(pp.y, pp.y);
                ulonglong2 v0 = *(const ulonglong2*)(kv + (kk + 0) * DD + dg * 4);
                ulonglong2 v1 = *(const ulonglong2*)(kv + (kk + 1) * DD + dg * 4);
                acc0 = fma2(px, v0.x, acc0);
                acc1 = fma2(px, v0.y, acc1);
                acc0 = fma2(py, v1.x, acc0);
                acc1 = fma2(py, v1.y, acc1);
            }
        }

        float2 a0 = upk2(acc0);
        float2 a1 = upk2(acc1);
        float4 o = make_float4(a0.x, a0.y, a1.x, a1.y);
        *(float4*)(Out + ((size_t)bh * SS + q0 + qg) * DD + dg * 4) = o;
    }
}

extern "C" void kernel_launch(void* const* d_in, const int* in_sizes, int n_in,
                              void* d_out, int out_size) {
    const float* q    = (const float*)d_in[0];
    const float* k    = (const float*)d_in[1];
    const float* v    = (const float*)d_in[2];
    const int*   mask = (const int*)d_in[3];

    float* out  = (float*)d_out;                                  // [B,H,S,D]
    float* prob = out + (size_t)BB * HH * SS * DD;                // [B,H,S,S]

    cudaFuncSetAttribute(sdpa_fused_kernel,
                         cudaFuncAttributeMaxDynamicSharedMemorySize, SMEM_BYTES);

    dim3 grid(BB * HH * (SS / QT));   // 4096 CTAs
    sdpa_fused_kernel<<<grid, NTH, SMEM_BYTES>>>(q, k, v, mask, out, prob);
}

// round 3
// speedup vs baseline: 3.2394x; 3.2394x over previous
#include <cuda_runtime.h>
#include <cuda_bf16.h>
#include <cstdint>

typedef uint32_t u32;

#define BB 2
#define HH 16
#define SS 2048
#define DD 64
#define QT 128
#define KT 128
#define NKB (SS/KT)
#define NTH 256
#define SCALE 0.125f

// ---- smem layout (bytes) ----
#define KPITCH 72               // bf16 elems per K row  (bank 4r+c: conflict-free frags)
#define VTPITCH 136             // bf16 elems per Vt row (bank 4r+c: conflict-free frags)
#define VSPITCH 68              // fp32 elems per V stage row (16B-aligned float4 rows)
#define OFF_KH  0
#define SZ_K    (KT*KPITCH*2)            // 18432
#define OFF_KL  (OFF_KH + SZ_K)
#define OFF_VTH (OFF_KL + SZ_K)          // 36864
#define SZ_VT   (DD*VTPITCH*2)           // 17408
#define OFF_VTL (OFF_VTH + SZ_VT)
#define OFF_VS  (OFF_VTL + SZ_VT)        // 71680
#define SZ_VS   (KT*VSPITCH*4)           // 34816
#define SMEM_TOTAL (OFF_VS + SZ_VS)      // 106496

__device__ u32 g_maskbits[SS * SS / 32];   // 512 KB bit-packed mask

__global__ void pack_mask_kernel(const int* __restrict__ mask) {
    int g = blockIdx.x * blockDim.x + threadIdx.x;      // 0 .. S*S-1
    u32 b = __ballot_sync(0xffffffffu, mask[g] != 0);
    if ((threadIdx.x & 31) == 0) g_maskbits[g >> 5] = b;
}

// hi/lo bf16 split of a float pair, packed as bf16x2
__device__ __forceinline__ u32 split2(float x, float y, u32& lo) {
    __nv_bfloat162 h = __floats2bfloat162_rn(x, y);
    float2 hf = __bfloat1622float2(h);
    __nv_bfloat162 l = __floats2bfloat162_rn(x - hf.x, y - hf.y);
    lo = *reinterpret_cast<u32*>(&l);
    return *reinterpret_cast<u32*>(&h);
}

__device__ __forceinline__ void mma16816(float c[4], const u32 a[4], u32 b0, u32 b1) {
    asm volatile("mma.sync.aligned.m16n8k16.row.col.f32.bf16.bf16.f32 "
        "{%0,%1,%2,%3}, {%4,%5,%6,%7}, {%8,%9}, {%0,%1,%2,%3};"
        : "+f"(c[0]), "+f"(c[1]), "+f"(c[2]), "+f"(c[3])
        : "r"(a[0]), "r"(a[1]), "r"(a[2]), "r"(a[3]), "r"(b0), "r"(b1));
}

// K block [128 x 64] fp32 -> Kh/Kl bf16, k-major, pitch KPITCH
__device__ __forceinline__ void fill_k(const float* __restrict__ src, char* sm, int t) {
    const float4* s4 = (const float4*)src;
    #pragma unroll
    for (int j = 0; j < 8; j++) {
        int i = t + j * NTH;
        int ks = i >> 4, dg = i & 15;
        float4 f = s4[i];
        u32 l01, l23;
        u32 h01 = split2(f.x, f.y, l01);
        u32 h23 = split2(f.z, f.w, l23);
        u32 off = (u32)(ks * (KPITCH * 2) + dg * 8);
        *(uint2*)(sm + OFF_KH + off) = make_uint2(h01, h23);
        *(uint2*)(sm + OFF_KL + off) = make_uint2(l01, l23);
    }
}

// V block [128 x 64] fp32 -> fp32 stage (pitch VSPITCH)
__device__ __forceinline__ void fill_vstage(const float* __restrict__ src, char* sm, int t) {
    const float4* s4 = (const float4*)src;
    float* vs = (float*)(sm + OFF_VS);
    #pragma unroll
    for (int j = 0; j < 8; j++) {
        int i = t + j * NTH;
        int ks = i >> 4, dg = i & 15;
        *(float4*)(vs + ks * VSPITCH + dg * 4) = s4[i];
    }
}

// fp32 stage -> transposed Vt[d][k] bf16 hi/lo
__device__ __forceinline__ void vt_convert(char* sm, int t) {
    const float* vs = (const float*)(sm + OFF_VS);
    int d = t & 63, k0 = (t >> 6) * 32;
    #pragma unroll
    for (int kk = 0; kk < 32; kk += 2) {
        float v0 = vs[(k0 + kk) * VSPITCH + d];
        float v1 = vs[(k0 + kk + 1) * VSPITCH + d];
        u32 lo; u32 hi = split2(v0, v1, lo);
        u32 off = (u32)(d * (VTPITCH * 2) + (k0 + kk) * 2);
        *(u32*)(sm + OFF_VTH + off) = hi;
        *(u32*)(sm + OFF_VTL + off) = lo;
    }
}

// S strip [16 q x 128 k] via 3-split bf16 mma
__device__ __forceinline__ void qk_compute(char* sm, float sacc[16][4],
                                           const u32 qh[4][4], const u32 ql[4][4],
                                           int gr, int c) {
    #pragma unroll
    for (int j = 0; j < 16; j++)
        #pragma unroll
        for (int x = 0; x < 4; x++) sacc[j][x] = 0.f;

    #pragma unroll
    for (int ks = 0; ks < 4; ks++) {
        #pragma unroll
        for (int j = 0; j < 16; j++) {
            u32 off = (u32)((j * 8 + gr) * (KPITCH * 2) + (ks * 16 + 2 * c) * 2);
            u32 bh0 = *(const u32*)(sm + OFF_KH + off);
            u32 bh1 = *(const u32*)(sm + OFF_KH + off + 16);
            u32 bl0 = *(const u32*)(sm + OFF_KL + off);
            u32 bl1 = *(const u32*)(sm + OFF_KL + off + 16);
            mma16816(sacc[j], qh[ks], bh0, bh1);
            mma16816(sacc[j], qh[ks], bl0, bl1);
            mma16816(sacc[j], ql[ks], bh0, bh1);
        }
    }
}

__global__ void __launch_bounds__(NTH, 1)
sdpa_mma_kernel(const float* __restrict__ Q, const float* __restrict__ K,
                const float* __restrict__ V,
                float* __restrict__ Out, float* __restrict__ Prob) {
    extern __shared__ char sm[];
    const int t = threadIdx.x;
    const int w = t >> 5, l = t & 31;
    const int gr = l >> 2, c = l & 3;

    const int qblk = blockIdx.x >> 5;    // 0..15
    const int bh   = blockIdx.x & 31;    // 0..31
    const int q0   = qblk * QT;
    const int qw0  = w * 16;             // warp's q-row base within tile

    const float* Kp = K + (size_t)bh * SS * DD;
    const float* Vp = V + (size_t)bh * SS * DD;

    // ---- Q fragments (resident, hi/lo) ----
    u32 qh[4][4], ql[4][4];
    {
        const float* Qp = Q + ((size_t)bh * SS + q0 + qw0) * DD;
        #pragma unroll
        for (int ks = 0; ks < 4; ks++) {
            const float* r0 = Qp + gr * DD + ks * 16 + 2 * c;
            const float* r1 = r0 + 8 * DD;
            float2 f00 = *(const float2*)(r0);
            float2 f10 = *(const float2*)(r1);
            float2 f01 = *(const float2*)(r0 + 8);
            float2 f11 = *(const float2*)(r1 + 8);
            qh[ks][0] = split2(f00.x, f00.y, ql[ks][0]);
            qh[ks][1] = split2(f10.x, f10.y, ql[ks][1]);
            qh[ks][2] = split2(f01.x, f01.y, ql[ks][2]);
            qh[ks][3] = split2(f11.x, f11.y, ql[ks][3]);
        }
    }

    const int mrow0 = q0 + qw0 + gr;       // mask/global q rows for this lane
    const uint4* mb = (const uint4*)g_maskbits;

    float sacc[16][4];
    float l0 = 0.f, l1 = 0.f;

    // =================== PASS 1: row sums of exp ===================
    for (int kb = 0; kb < NKB; kb++) {
        __syncthreads();
        fill_k(Kp + (size_t)kb * KT * DD, sm, t);
        __syncthreads();
        qk_compute(sm, sacc, qh, ql, gr, c);

        uint4 m0v = mb[mrow0 * 16 + kb];
        uint4 m1v = mb[(mrow0 + 8) * 16 + kb];
        u32 m0a[4] = {m0v.x, m0v.y, m0v.z, m0v.w};
        u32 m1a[4] = {m1v.x, m1v.y, m1v.z, m1v.w};
        #pragma unroll
        for (int j = 0; j < 16; j++) {
            u32 w0 = m0a[j >> 2], w1 = m1a[j >> 2];
            int sh = 8 * (j & 3) + 2 * c;
            l0 += (float)((w0 >> sh) & 1u)       * __expf(sacc[j][0] * SCALE);
            l0 += (float)((w0 >> (sh + 1)) & 1u) * __expf(sacc[j][1] * SCALE);
            l1 += (float)((w1 >> sh) & 1u)       * __expf(sacc[j][2] * SCALE);
            l1 += (float)((w1 >> (sh + 1)) & 1u) * __expf(sacc[j][3] * SCALE);
        }
    }
    // quad reduce (lanes of a quad hold disjoint columns of the same rows)
    l0 += __shfl_xor_sync(0xffffffffu, l0, 1);
    l0 += __shfl_xor_sync(0xffffffffu, l0, 2);
    l1 += __shfl_xor_sync(0xffffffffu, l1, 1);
    l1 += __shfl_xor_sync(0xffffffffu, l1, 2);
    const float inv0 = 1.f / l0, inv1 = 1.f / l1;

    // =================== PASS 2: P write + O = P@V ===================
    float oacc[8][4];
    #pragma unroll
    for (int on = 0; on < 8; on++)
        #pragma unroll
        for (int x = 0; x < 4; x++) oacc[on][x] = 0.f;

    const size_t gq = (size_t)bh * SS + q0 + qw0;
    float* pr0base = Prob + (gq + gr) * SS + 2 * c;
    float* pr1base = pr0base + 8 * SS;

    for (int kb = 0; kb < NKB; kb++) {
        __syncthreads();
        fill_k(Kp + (size_t)kb * KT * DD, sm, t);
        fill_vstage(Vp + (size_t)kb * KT * DD, sm, t);
        __syncthreads();
        vt_convert(sm, t);                      // Vt for this kb
        qk_compute(sm, sacc, qh, ql, gr, c);    // recompute S (bitwise = pass 1)
        __syncthreads();                        // Vt visible to all warps

        uint4 m0v = mb[mrow0 * 16 + kb];
        uint4 m1v = mb[(mrow0 + 8) * 16 + kb];
        u32 m0a[4] = {m0v.x, m0v.y, m0v.z, m0v.w};
        u32 m1a[4] = {m1v.x, m1v.y, m1v.z, m1v.w};

        float* p0 = pr0base + (size_t)kb * KT;
        float* p1 = pr1base + (size_t)kb * KT;

        #pragma unroll
        for (int jp = 0; jp < 8; jp++) {
            u32 aH[4], aL[4];
            #pragma unroll
            for (int jj = 0; jj < 2; jj++) {
                int j = 2 * jp + jj;
                u32 w0 = m0a[j >> 2], w1 = m1a[j >> 2];
                int sh = 8 * (j & 3) + 2 * c;
                float e00 = (float)((w0 >> sh) & 1u)       * __expf(sacc[j][0] * SCALE) * inv0;
                float e01 = (float)((w0 >> (sh + 1)) & 1u) * __expf(sacc[j][1] * SCALE) * inv0;
                float e10 = (float)((w1 >> sh) & 1u)       * __expf(sacc[j][2] * SCALE) * inv1;
                float e11 = (float)((w1 >> (sh + 1)) & 1u) * __expf(sacc[j][3] * SCALE) * inv1;
                *(float2*)(p0 + j * 8) = make_float2(e00, e01);
                *(float2*)(p1 + j * 8) = make_float2(e10, e11);
                aH[2 * jj]     = split2(e00, e01, aL[2 * jj]);
                aH[2 * jj + 1] = split2(e10, e11, aL[2 * jj + 1]);
            }
            #pragma unroll
            for (int on = 0; on < 8; on++) {
                u32 off = (u32)((on * 8 + gr) * (VTPITCH * 2) + (jp * 16 + 2 * c) * 2);
                u32 vh0 = *(const u32*)(sm + OFF_VTH + off);
                u32 vh1 = *(const u32*)(sm + OFF_VTH + off + 16);
                u32 vl0 = *(const u32*)(sm + OFF_VTL + off);
                u32 vl1 = *(const u32*)(sm + OFF_VTL + off + 16);
                mma16816(oacc[on], aH, vh0, vh1);
                mma16816(oacc[on], aH, vl0, vl1);
                mma16816(oacc[on], aL, vh0, vh1);
            }
        }
    }

    // ---- O writeout ----
    {
        float* o0 = Out + (gq + gr) * DD + 2 * c;
        float* o1 = o0 + 8 * DD;
        #pragma unroll
        for (int on = 0; on < 8; on++) {
            *(float2*)(o0 + on * 8) = make_float2(oacc[on][0], oacc[on][1]);
            *(float2*)(o1 + on * 8) = make_float2(oacc[on][2], oacc[on][3]);
        }
    }
}

extern "C" void kernel_launch(void* const* d_in, const int* in_sizes, int n_in,
                              void* d_out, int out_size) {
    const float* q    = (const float*)d_in[0];
    const float* k    = (const float*)d_in[1];
    const float* v    = (const float*)d_in[2];
    const int*   mask = (const int*)d_in[3];

    float* out  = (float*)d_out;                          // [B,H,S,D]
    float* prob = out + (size_t)BB * HH * SS * DD;        // [B,H,S,S]

    pack_mask_kernel<<<(SS * SS) / NTH, NTH>>>(mask);

    cudaFuncSetAttribute(sdpa_mma_kernel,
                         cudaFuncAttributeMaxDynamicSharedMemorySize, SMEM_TOTAL);
    dim3 grid(BB * HH * (SS / QT));   // 512 CTAs
    sdpa_mma_kernel<<<grid, NTH, SMEM_TOTAL>>>(q, k, v, out, prob);
}

// round 4
// speedup vs baseline: 4.3699x; 1.3490x over previous
#include <cuda_runtime.h>
#include <cuda_fp16.h>
#include <cstdint>

typedef uint32_t u32;

#define BB 2
#define HH 16
#define SS 2048
#define DD 64
#define QT 128
#define KT 128
#define NKB (SS/KT)
#define NTH 256
#define CEXP 0.18033688011112042f   // 0.125 * log2(e)

#define RPB 144                      // smem row pitch bytes (72 halves)
#define TILE_B (KT*RPB)              // 18432 per matrix
#define OFF_KH 0
#define OFF_KL (OFF_KH + TILE_B)
#define OFF_VH (OFF_KL + TILE_B)
#define OFF_VL (OFF_VH + TILE_B)
#define SMEM_TOTAL (4*TILE_B)        // 73728 B

__device__ u32 g_maskbits[SS * SS / 32];   // 512 KB bit-packed mask

__global__ void pack_mask_kernel(const int* __restrict__ mask) {
    int g = blockIdx.x * blockDim.x + threadIdx.x;
    u32 b = __ballot_sync(0xffffffffu, mask[g] != 0);
    if ((threadIdx.x & 31) == 0) g_maskbits[g >> 5] = b;
}

__device__ __forceinline__ float ex2f(float x) {
    float r; asm("ex2.approx.f32 %0, %1;" : "=f"(r) : "f"(x)); return r;
}

// fp16 hi/lo split of a float pair, packed half2
__device__ __forceinline__ u32 splith(float x, float y, u32& lo) {
    __half2 h = __floats2half2_rn(x, y);
    float2 hf = __half22float2(h);
    __half2 lw = __floats2half2_rn(x - hf.x, y - hf.y);
    lo = *reinterpret_cast<u32*>(&lw);
    return *reinterpret_cast<u32*>(&h);
}
__device__ __forceinline__ u32 packh(float x, float y) {
    __half2 h = __floats2half2_rn(x, y);
    return *reinterpret_cast<u32*>(&h);
}

__device__ __forceinline__ void mma_f16(float c[4], const u32 a[4], u32 b0, u32 b1) {
    asm volatile("mma.sync.aligned.m16n8k16.row.col.f32.f16.f16.f32 "
        "{%0,%1,%2,%3}, {%4,%5,%6,%7}, {%8,%9}, {%0,%1,%2,%3};"
        : "+f"(c[0]), "+f"(c[1]), "+f"(c[2]), "+f"(c[3])
        : "r"(a[0]), "r"(a[1]), "r"(a[2]), "r"(a[3]), "r"(b0), "r"(b1));
}

__device__ __forceinline__ void ldsm4(u32& r0, u32& r1, u32& r2, u32& r3, u32 a) {
    asm volatile("ldmatrix.sync.aligned.m8n8.x4.shared.b16 {%0,%1,%2,%3}, [%4];"
        : "=r"(r0), "=r"(r1), "=r"(r2), "=r"(r3) : "r"(a));
}
__device__ __forceinline__ void ldsm4t(u32& r0, u32& r1, u32& r2, u32& r3, u32 a) {
    asm volatile("ldmatrix.sync.aligned.m8n8.x4.trans.shared.b16 {%0,%1,%2,%3}, [%4];"
        : "=r"(r0), "=r"(r1), "=r"(r2), "=r"(r3) : "r"(a));
}

// ---- gmem tile prefetch (registers) + smem conversion ----
__device__ __forceinline__ void ldg_tile(const float* __restrict__ src, float4 r[8], int t) {
    const float4* s4 = (const float4*)src;
    #pragma unroll
    for (int j = 0; j < 8; j++) r[j] = s4[t + j * NTH];
}
__device__ __forceinline__ void sts_hilo(const float4 r[8], char* hi, char* lo, int t) {
    #pragma unroll
    for (int j = 0; j < 8; j++) {
        int i = t + j * NTH;
        int row = i >> 4, dg = i & 15;
        u32 l01, l23;
        u32 h01 = splith(r[j].x, r[j].y, l01);
        u32 h23 = splith(r[j].z, r[j].w, l23);
        u32 off = (u32)(row * RPB + dg * 8);
        *(uint2*)(hi + off) = make_uint2(h01, h23);
        *(uint2*)(lo + off) = make_uint2(l01, l23);
    }
}
__device__ __forceinline__ void sts_hi(const float4 r[8], char* hi, int t) {
    #pragma unroll
    for (int j = 0; j < 8; j++) {
        int i = t + j * NTH;
        int row = i >> 4, dg = i & 15;
        u32 h01 = packh(r[j].x, r[j].y);
        u32 h23 = packh(r[j].z, r[j].w);
        *(uint2*)(hi + (u32)(row * RPB + dg * 8)) = make_uint2(h01, h23);
    }
}

__global__ void __launch_bounds__(NTH, 1)
sdpa_mma_kernel(const float* __restrict__ Q, const float* __restrict__ K,
                const float* __restrict__ V,
                float* __restrict__ Out, float* __restrict__ Prob) {
    extern __shared__ char sm[];
    u32 sb;
    asm("{ .reg .u64 t; cvta.to.shared.u64 t, %1; cvt.u32.u64 %0, t; }" : "=r"(sb) : "l"(sm));

    const int t = threadIdx.x;
    const int w = t >> 5, l = t & 31;
    const int gr = l >> 2, c = l & 3;

    const int qblk = blockIdx.x >> 5;    // 0..15 (consecutive CTAs share mask rows)
    const int bh   = blockIdx.x & 31;    // 0..31
    const int q0   = qblk * QT;
    const int qw0  = w * 16;

    const float* Kp = K + (size_t)bh * SS * DD;
    const float* Vp = V + (size_t)bh * SS * DD;

    // ---- resident Q fragments, fp16 hi/lo ----
    u32 qh[4][4], ql[4][4];
    {
        const float* Qp = Q + ((size_t)bh * SS + q0 + qw0) * DD;
        #pragma unroll
        for (int ks = 0; ks < 4; ks++) {
            const float* r0 = Qp + gr * DD + ks * 16 + 2 * c;
            const float* r1 = r0 + 8 * DD;
            float2 f00 = *(const float2*)(r0);
            float2 f10 = *(const float2*)(r1);
            float2 f01 = *(const float2*)(r0 + 8);
            float2 f11 = *(const float2*)(r1 + 8);
            qh[ks][0] = splith(f00.x, f00.y, ql[ks][0]);
            qh[ks][1] = splith(f10.x, f10.y, ql[ks][1]);
            qh[ks][2] = splith(f01.x, f01.y, ql[ks][2]);
            qh[ks][3] = splith(f11.x, f11.y, ql[ks][3]);
        }
    }

    const int mrow0 = q0 + qw0 + gr;
    const uint4* mb = (const uint4*)g_maskbits;

    // ldmatrix lane offsets
    const u32 loffk = (u32)(((((l >> 4) & 1) * 8) + (l & 7)) * RPB + ((l >> 3) & 1) * 16);
    const u32 loffv = (u32)(((((l >> 3) & 1) * 8) + (l & 7)) * RPB + ((l >> 4) & 1) * 16);
    const u32 aKH = sb + OFF_KH, aKL = sb + OFF_KL;
    const u32 aVH = sb + OFF_VH, aVL = sb + OFF_VL;

    float sacc[16][4];
    float l0 = 0.f, l1 = 0.f;
    float4 kreg[8], vreg[8];

    // =================== PASS 1: row sums (hi*hi only) ===================
    ldg_tile(Kp, kreg, t);
    for (int kb = 0; kb < NKB; kb++) {
        __syncthreads();
        sts_hi(kreg, sm + OFF_KH, t);
        __syncthreads();
        if (kb + 1 < NKB) ldg_tile(Kp + (size_t)(kb + 1) * KT * DD, kreg, t);

        uint4 m0v = mb[(size_t)mrow0 * 16 + kb];
        uint4 m1v = mb[(size_t)(mrow0 + 8) * 16 + kb];

        #pragma unroll
        for (int j = 0; j < 16; j++)
            #pragma unroll
            for (int x = 0; x < 4; x++) sacc[j][x] = 0.f;

        #pragma unroll
        for (int ks = 0; ks < 4; ks++)
            #pragma unroll
            for (int jp = 0; jp < 8; jp++) {
                u32 b0, b1, b2, b3;
                ldsm4(b0, b1, b2, b3, aKH + (u32)(jp * (16 * RPB) + ks * 32) + loffk);
                mma_f16(sacc[2 * jp],     qh[ks], b0, b1);
                mma_f16(sacc[2 * jp + 1], qh[ks], b2, b3);
            }

        u32 m0a[4] = {m0v.x, m0v.y, m0v.z, m0v.w};
        u32 m1a[4] = {m1v.x, m1v.y, m1v.z, m1v.w};
        #pragma unroll
        for (int j = 0; j < 16; j++) {
            u32 w0 = m0a[j >> 2], w1 = m1a[j >> 2];
            int sh = 8 * (j & 3) + 2 * c;
            l0 += (float)((w0 >> sh) & 1u)       * ex2f(sacc[j][0] * CEXP);
            l0 += (float)((w0 >> (sh + 1)) & 1u) * ex2f(sacc[j][1] * CEXP);
            l1 += (float)((w1 >> sh) & 1u)       * ex2f(sacc[j][2] * CEXP);
            l1 += (float)((w1 >> (sh + 1)) & 1u) * ex2f(sacc[j][3] * CEXP);
        }
    }
    l0 += __shfl_xor_sync(0xffffffffu, l0, 1);
    l0 += __shfl_xor_sync(0xffffffffu, l0, 2);
    l1 += __shfl_xor_sync(0xffffffffu, l1, 1);
    l1 += __shfl_xor_sync(0xffffffffu, l1, 2);
    const float inv0 = 1.f / l0, inv1 = 1.f / l1;

    // =================== PASS 2: P write + O = P@V ===================
    float oacc[8][4];
    #pragma unroll
    for (int on = 0; on < 8; on++)
        #pragma unroll
        for (int x = 0; x < 4; x++) oacc[on][x] = 0.f;

    const size_t gq = (size_t)bh * SS + q0 + qw0;
    float* pr0base = Prob + (gq + gr) * SS + 2 * c;
    float* pr1base = pr0base + 8 * SS;

    ldg_tile(Kp, kreg, t);
    ldg_tile(Vp, vreg, t);

    for (int kb = 0; kb < NKB; kb++) {
        __syncthreads();
        sts_hilo(kreg, sm + OFF_KH, sm + OFF_KL, t);
        sts_hilo(vreg, sm + OFF_VH, sm + OFF_VL, t);
        __syncthreads();
        if (kb + 1 < NKB) {
            ldg_tile(Kp + (size_t)(kb + 1) * KT * DD, kreg, t);
            ldg_tile(Vp + (size_t)(kb + 1) * KT * DD, vreg, t);
        }

        uint4 m0v = mb[(size_t)mrow0 * 16 + kb];
        uint4 m1v = mb[(size_t)(mrow0 + 8) * 16 + kb];

        #pragma unroll
        for (int j = 0; j < 16; j++)
            #pragma unroll
            for (int x = 0; x < 4; x++) sacc[j][x] = 0.f;

        // QK, 3-term fp16 split
        #pragma unroll
        for (int ks = 0; ks < 4; ks++)
            #pragma unroll
            for (int jp = 0; jp < 8; jp++) {
                u32 h0, h1, h2, h3, g0, g1, g2, g3;
                u32 off = (u32)(jp * (16 * RPB) + ks * 32) + loffk;
                ldsm4(h0, h1, h2, h3, aKH + off);
                ldsm4(g0, g1, g2, g3, aKL + off);
                mma_f16(sacc[2 * jp],     qh[ks], h0, h1);
                mma_f16(sacc[2 * jp],     ql[ks], h0, h1);
                mma_f16(sacc[2 * jp],     qh[ks], g0, g1);
                mma_f16(sacc[2 * jp + 1], qh[ks], h2, h3);
                mma_f16(sacc[2 * jp + 1], ql[ks], h2, h3);
                mma_f16(sacc[2 * jp + 1], qh[ks], g2, g3);
            }

        u32 m0a[4] = {m0v.x, m0v.y, m0v.z, m0v.w};
        u32 m1a[4] = {m1v.x, m1v.y, m1v.z, m1v.w};
        float* p0 = pr0base + (size_t)kb * KT;
        float* p1 = pr1base + (size_t)kb * KT;

        #pragma unroll
        for (int jp = 0; jp < 8; jp++) {
            u32 aH[4], aL[4];
            #pragma unroll
            for (int jj = 0; jj < 2; jj++) {
                int j = 2 * jp + jj;
                u32 w0 = m0a[j >> 2], w1 = m1a[j >> 2];
                int sh = 8 * (j & 3) + 2 * c;
                float e00 = (float)((w0 >> sh) & 1u)       * ex2f(sacc[j][0] * CEXP) * inv0;
                float e01 = (float)((w0 >> (sh + 1)) & 1u) * ex2f(sacc[j][1] * CEXP) * inv0;
                float e10 = (float)((w1 >> sh) & 1u)       * ex2f(sacc[j][2] * CEXP) * inv1;
                float e11 = (float)((w1 >> (sh + 1)) & 1u) * ex2f(sacc[j][3] * CEXP) * inv1;
                *(float2*)(p0 + j * 8) = make_float2(e00, e01);
                *(float2*)(p1 + j * 8) = make_float2(e10, e11);
                aH[2 * jj]     = splith(e00, e01, aL[2 * jj]);
                aH[2 * jj + 1] = splith(e10, e11, aL[2 * jj + 1]);
            }
            // PV: B-frags via ldmatrix.trans from k-major V
            #pragma unroll
            for (int op = 0; op < 4; op++) {
                u32 v0, v1, v2, v3, u0, u1, u2, u3;
                u32 off = (u32)(jp * (16 * RPB) + op * 32) + loffv;
                ldsm4t(v0, v1, v2, v3, aVH + off);
                ldsm4t(u0, u1, u2, u3, aVL + off);
                mma_f16(oacc[2 * op],     aH, v0, v1);
                mma_f16(oacc[2 * op],     aL, v0, v1);
                mma_f16(oacc[2 * op],     aH, u0, u1);
                mma_f16(oacc[2 * op + 1], aH, v2, v3);
                mma_f16(oacc[2 * op + 1], aL, v2, v3);
                mma_f16(oacc[2 * op + 1], aH, u2, u3);
            }
        }
    }

    // ---- O writeout ----
    {
        float* o0 = Out + (gq + gr) * DD + 2 * c;
        float* o1 = o0 + 8 * DD;
        #pragma unroll
        for (int on = 0; on < 8; on++) {
            *(float2*)(o0 + on * 8) = make_float2(oacc[on][0], oacc[on][1]);
            *(float2*)(o1 + on * 8) = make_float2(oacc[on][2], oacc[on][3]);
        }
    }
}

extern "C" void kernel_launch(void* const* d_in, const int* in_sizes, int n_in,
                              void* d_out, int out_size) {
    const float* q    = (const float*)d_in[0];
    const float* k    = (const float*)d_in[1];
    const float* v    = (const float*)d_in[2];
    const int*   mask = (const int*)d_in[3];

    float* out  = (float*)d_out;                          // [B,H,S,D]
    float* prob = out + (size_t)BB * HH * SS * DD;        // [B,H,S,S]

    pack_mask_kernel<<<(SS * SS) / NTH, NTH>>>(mask);

    cudaFuncSetAttribute(sdpa_mma_kernel,
                         cudaFuncAttributeMaxDynamicSharedMemorySize, SMEM_TOTAL);
    dim3 grid(BB * HH * (SS / QT));   // 512 CTAs
    sdpa_mma_kernel<<<grid, NTH, SMEM_TOTAL>>>(q, k, v, out, prob);
}

// round 5
// speedup vs baseline: 5.2932x; 1.2113x over previous
#include <cuda_runtime.h>
#include <cuda_fp16.h>
#include <cstdint>

typedef uint32_t u32;

#define BB 2
#define HH 16
#define SS 2048
#define DD 64
#define QT 128
#define KT 128
#define NKB (SS/KT)
#define NTH 256
#define CEXP 0.18033688011112042f   // 0.125 * log2(e)
#define KVELEM (BB*HH*SS*DD)        // 4,194,304

#define OFF_KH 0
#define OFF_KL 16384
#define OFF_VH 32768
#define OFF_VL 49152
#define SMEM_TOTAL 65536

__device__ u32   g_maskbits[SS * SS / 32];                 // 512 KB
__device__ uint4 g_kh[KVELEM / 8], g_kl[KVELEM / 8];       // 8 MB each
__device__ uint4 g_vh[KVELEM / 8], g_vl[KVELEM / 8];

__global__ void pack_mask_kernel(const int* __restrict__ mask) {
    int g = blockIdx.x * blockDim.x + threadIdx.x;
    u32 b = __ballot_sync(0xffffffffu, mask[g] != 0);
    if ((threadIdx.x & 31) == 0) g_maskbits[g >> 5] = b;
}

__device__ __forceinline__ float ex2f(float x) {
    float r; asm("ex2.approx.f32 %0, %1;" : "=f"(r) : "f"(x)); return r;
}
__device__ __forceinline__ u32 splith(float x, float y, u32& lo) {
    __half2 h = __floats2half2_rn(x, y);
    float2 hf = __half22float2(h);
    __half2 lw = __floats2half2_rn(x - hf.x, y - hf.y);
    lo = *reinterpret_cast<u32*>(&lw);
    return *reinterpret_cast<u32*>(&h);
}

__global__ void split_kv_kernel(const float* __restrict__ K, const float* __restrict__ V) {
    int i = blockIdx.x * blockDim.x + threadIdx.x;   // uint4 index (8 halves)
    const float4* k4 = (const float4*)K;
    const float4* v4 = (const float4*)V;
    float4 a = k4[2 * i], b = k4[2 * i + 1];
    u32 l0, l1, l2, l3;
    u32 h0 = splith(a.x, a.y, l0), h1 = splith(a.z, a.w, l1);
    u32 h2 = splith(b.x, b.y, l2), h3 = splith(b.z, b.w, l3);
    g_kh[i] = make_uint4(h0, h1, h2, h3);
    g_kl[i] = make_uint4(l0, l1, l2, l3);
    a = v4[2 * i]; b = v4[2 * i + 1];
    h0 = splith(a.x, a.y, l0); h1 = splith(a.z, a.w, l1);
    h2 = splith(b.x, b.y, l2); h3 = splith(b.z, b.w, l3);
    g_vh[i] = make_uint4(h0, h1, h2, h3);
    g_vl[i] = make_uint4(l0, l1, l2, l3);
}

__device__ __forceinline__ void mma_f16(float c[4], const u32 a[4], u32 b0, u32 b1) {
    asm volatile("mma.sync.aligned.m16n8k16.row.col.f32.f16.f16.f32 "
        "{%0,%1,%2,%3}, {%4,%5,%6,%7}, {%8,%9}, {%0,%1,%2,%3};"
        : "+f"(c[0]), "+f"(c[1]), "+f"(c[2]), "+f"(c[3])
        : "r"(a[0]), "r"(a[1]), "r"(a[2]), "r"(a[3]), "r"(b0), "r"(b1));
}
__device__ __forceinline__ void ldsm4(u32& r0, u32& r1, u32& r2, u32& r3, u32 a) {
    asm volatile("ldmatrix.sync.aligned.m8n8.x4.shared.b16 {%0,%1,%2,%3}, [%4];"
        : "=r"(r0), "=r"(r1), "=r"(r2), "=r"(r3) : "r"(a));
}
__device__ __forceinline__ void ldsm4t(u32& r0, u32& r1, u32& r2, u32& r3, u32 a) {
    asm volatile("ldmatrix.sync.aligned.m8n8.x4.trans.shared.b16 {%0,%1,%2,%3}, [%4];"
        : "=r"(r0), "=r"(r1), "=r"(r2), "=r"(r3) : "r"(a));
}
__device__ __forceinline__ void cpa16(u32 dst, const void* src) {
    asm volatile("cp.async.cg.shared.global [%0], [%1], 16;" :: "r"(dst), "l"(src));
}
#define CP_COMMIT() asm volatile("cp.async.commit_group;" ::: "memory")
#define CP_WAIT0()  asm volatile("cp.async.wait_group 0;" ::: "memory")

// XOR-swizzled dst offset for linear 16B chunk i of a [128 x 64h] tile
__device__ __forceinline__ u32 swz_dst(int i) {
    return (u32)(((i >> 3) << 7) + ((((i) & 7) ^ ((i >> 3) & 7)) << 4));
}

__global__ void __launch_bounds__(NTH, 2)
sdpa_mma_kernel(const float* __restrict__ Q,
                float* __restrict__ Out, float* __restrict__ Prob) {
    extern __shared__ char sm[];
    u32 sb;
    asm("{ .reg .u64 t; cvta.to.shared.u64 t, %1; cvt.u32.u64 %0, t; }" : "=r"(sb) : "l"(sm));

    const int t = threadIdx.x;
    const int w = t >> 5, l = t & 31;
    const int gr = l >> 2, c = l & 3;

    const int qblk = blockIdx.x >> 5;   // 0..15
    const int bh   = blockIdx.x & 31;   // 0..31
    const int q0   = qblk * QT;
    const int qw0  = w * 16;

    // pre-split K/V tile bases (uint4 units; one kb tile = 1024 chunks)
    const size_t bhbase = (size_t)bh * (SS * DD / 8);
    const uint4* pkh = g_kh + bhbase;
    const uint4* pkl = g_kl + bhbase;
    const uint4* pvh = g_vh + bhbase;
    const uint4* pvl = g_vl + bhbase;

    // ---- resident Q fragments (fp16 hi/lo) ----
    u32 qh[4][4], ql[4][4];
    {
        const float* Qp = Q + ((size_t)bh * SS + q0 + qw0) * DD;
        #pragma unroll
        for (int ks = 0; ks < 4; ks++) {
            const float* r0 = Qp + gr * DD + ks * 16 + 2 * c;
            const float* r1 = r0 + 8 * DD;
            float2 f00 = *(const float2*)(r0);
            float2 f10 = *(const float2*)(r1);
            float2 f01 = *(const float2*)(r0 + 8);
            float2 f11 = *(const float2*)(r1 + 8);
            qh[ks][0] = splith(f00.x, f00.y, ql[ks][0]);
            qh[ks][1] = splith(f10.x, f10.y, ql[ks][1]);
            qh[ks][2] = splith(f01.x, f01.y, ql[ks][2]);
            qh[ks][3] = splith(f11.x, f11.y, ql[ks][3]);
        }
    }

    const int mrow0 = q0 + qw0 + gr;
    const u32* mw0 = g_maskbits + (size_t)mrow0 * (SS / 32);
    const u32* mw1 = mw0 + 8 * (SS / 32);

    // ldmatrix lane constants
    const int rl  = ((l >> 4) & 1) * 8 + (l & 7);   // QK rows
    const int clk = (l >> 3) & 1;
    const u32 lkA = (u32)(rl << 7), lks = (u32)(rl & 7);
    const int rv  = ((l >> 3) & 1) * 8 + (l & 7);   // PV (trans) rows
    const int cv  = (l >> 4) & 1;
    const u32 lvA = (u32)(rv << 7), lvs = (u32)(rv & 7);

    const u32 aKH = sb + OFF_KH, aKL = sb + OFF_KL;
    const u32 aVH = sb + OFF_VH, aVL = sb + OFF_VL;

    float l0 = 0.f, l1 = 0.f;

    // =================== PASS 1: row sums (hi*hi only) ===================
    for (int kb = 0; kb < NKB; kb++) {
        __syncthreads();
        #pragma unroll
        for (int j = 0; j < 4; j++) {
            int i = t + j * NTH;
            cpa16(aKH + swz_dst(i), pkh + (size_t)kb * 1024 + i);
        }
        CP_COMMIT(); CP_WAIT0();
        __syncthreads();

        #pragma unroll
        for (int jp = 0; jp < 8; jp++) {
            float s0[4] = {0.f, 0.f, 0.f, 0.f}, s1[4] = {0.f, 0.f, 0.f, 0.f};
            #pragma unroll
            for (int ks = 0; ks < 4; ks++) {
                u32 b0, b1, b2, b3;
                u32 a = aKH + (u32)(jp * 2048) + lkA + ((((u32)(ks << 1) | clk) ^ lks) << 4);
                ldsm4(b0, b1, b2, b3, a);
                mma_f16(s0, qh[ks], b0, b1);
                mma_f16(s1, qh[ks], b2, b3);
            }
            u32 w0 = mw0[kb * 4 + (jp >> 1)];
            u32 w1 = mw1[kb * 4 + (jp >> 1)];
            int sh = ((jp & 1) << 4) + 2 * c;
            l0 += (float)((w0 >> sh) & 1u)        * ex2f(s0[0] * CEXP);
            l0 += (float)((w0 >> (sh + 1)) & 1u)  * ex2f(s0[1] * CEXP);
            l1 += (float)((w1 >> sh) & 1u)        * ex2f(s0[2] * CEXP);
            l1 += (float)((w1 >> (sh + 1)) & 1u)  * ex2f(s0[3] * CEXP);
            l0 += (float)((w0 >> (sh + 8)) & 1u)  * ex2f(s1[0] * CEXP);
            l0 += (float)((w0 >> (sh + 9)) & 1u)  * ex2f(s1[1] * CEXP);
            l1 += (float)((w1 >> (sh + 8)) & 1u)  * ex2f(s1[2] * CEXP);
            l1 += (float)((w1 >> (sh + 9)) & 1u)  * ex2f(s1[3] * CEXP);
        }
    }
    l0 += __shfl_xor_sync(0xffffffffu, l0, 1);
    l0 += __shfl_xor_sync(0xffffffffu, l0, 2);
    l1 += __shfl_xor_sync(0xffffffffu, l1, 1);
    l1 += __shfl_xor_sync(0xffffffffu, l1, 2);
    const float inv0 = 1.f / l0, inv1 = 1.f / l1;

    // =================== PASS 2: P write + O = P@V ===================
    float oacc[8][4];
    #pragma unroll
    for (int on = 0; on < 8; on++)
        #pragma unroll
        for (int x = 0; x < 4; x++) oacc[on][x] = 0.f;

    const size_t gq = (size_t)bh * SS + q0 + qw0;
    float* pr0base = Prob + (gq + gr) * SS + 2 * c;
    float* pr1base = pr0base + 8 * SS;

    for (int kb = 0; kb < NKB; kb++) {
        __syncthreads();
        #pragma unroll
        for (int j = 0; j < 4; j++) {
            int i = t + j * NTH;
            const size_t gi = (size_t)kb * 1024 + i;
            u32 d = swz_dst(i);
            cpa16(aKH + d, pkh + gi);
            cpa16(aKL + d, pkl + gi);
            cpa16(aVH + d, pvh + gi);
            cpa16(aVL + d, pvl + gi);
        }
        CP_COMMIT(); CP_WAIT0();
        __syncthreads();

        float* p0 = pr0base + (size_t)kb * KT;
        float* p1 = pr1base + (size_t)kb * KT;

        #pragma unroll
        for (int jp = 0; jp < 8; jp++) {
            float s0[4] = {0.f, 0.f, 0.f, 0.f}, s1[4] = {0.f, 0.f, 0.f, 0.f};
            #pragma unroll
            for (int ks = 0; ks < 4; ks++) {
                u32 h0, h1, h2, h3, g0, g1, g2, g3;
                u32 off = (u32)(jp * 2048) + lkA + ((((u32)(ks << 1) | clk) ^ lks) << 4);
                ldsm4(h0, h1, h2, h3, aKH + off);
                ldsm4(g0, g1, g2, g3, aKL + off);
                mma_f16(s0, qh[ks], h0, h1);
                mma_f16(s0, ql[ks], h0, h1);
                mma_f16(s0, qh[ks], g0, g1);
                mma_f16(s1, qh[ks], h2, h3);
                mma_f16(s1, ql[ks], h2, h3);
                mma_f16(s1, qh[ks], g2, g3);
            }

            u32 w0 = mw0[kb * 4 + (jp >> 1)];
            u32 w1 = mw1[kb * 4 + (jp >> 1)];
            int sh = ((jp & 1) << 4) + 2 * c;

            u32 aH[4], aL[4];
            {
                float e00 = (float)((w0 >> sh) & 1u)       * ex2f(s0[0] * CEXP) * inv0;
                float e01 = (float)((w0 >> (sh + 1)) & 1u) * ex2f(s0[1] * CEXP) * inv0;
                float e10 = (float)((w1 >> sh) & 1u)       * ex2f(s0[2] * CEXP) * inv1;
                float e11 = (float)((w1 >> (sh + 1)) & 1u) * ex2f(s0[3] * CEXP) * inv1;
                __stcs((float2*)(p0 + (2 * jp) * 8), make_float2(e00, e01));
                __stcs((float2*)(p1 + (2 * jp) * 8), make_float2(e10, e11));
                aH[0] = splith(e00, e01, aL[0]);
                aH[1] = splith(e10, e11, aL[1]);
            }
            {
                float e00 = (float)((w0 >> (sh + 8)) & 1u) * ex2f(s1[0] * CEXP) * inv0;
                float e01 = (float)((w0 >> (sh + 9)) & 1u) * ex2f(s1[1] * CEXP) * inv0;
                float e10 = (float)((w1 >> (sh + 8)) & 1u) * ex2f(s1[2] * CEXP) * inv1;
                float e11 = (float)((w1 >> (sh + 9)) & 1u) * ex2f(s1[3] * CEXP) * inv1;
                __stcs((float2*)(p0 + (2 * jp + 1) * 8), make_float2(e00, e01));
                __stcs((float2*)(p1 + (2 * jp + 1) * 8), make_float2(e10, e11));
                aH[2] = splith(e00, e01, aL[2]);
                aH[3] = splith(e10, e11, aL[3]);
            }

            #pragma unroll
            for (int op = 0; op < 4; op++) {
                u32 v0, v1, v2, v3, u0, u1, u2, u3;
                u32 off = (u32)(jp * 2048) + lvA + ((((u32)(op << 1) | cv) ^ lvs) << 4);
                ldsm4t(v0, v1, v2, v3, aVH + off);
                ldsm4t(u0, u1, u2, u3, aVL + off);
                mma_f16(oacc[2 * op],     aH, v0, v1);
                mma_f16(oacc[2 * op],     aL, v0, v1);
                mma_f16(oacc[2 * op],     aH, u0, u1);
                mma_f16(oacc[2 * op + 1], aH, v2, v3);
                mma_f16(oacc[2 * op + 1], aL, v2, v3);
                mma_f16(oacc[2 * op + 1], aH, u2, u3);
            }
        }
    }

    // ---- O writeout ----
    {
        float* o0 = Out + (gq + gr) * DD + 2 * c;
        float* o1 = o0 + 8 * DD;
        #pragma unroll
        for (int on = 0; on < 8; on++) {
            *(float2*)(o0 + on * 8) = make_float2(oacc[on][0], oacc[on][1]);
            *(float2*)(o1 + on * 8) = make_float2(oacc[on][2], oacc[on][3]);
        }
    }
}

extern "C" void kernel_launch(void* const* d_in, const int* in_sizes, int n_in,
                              void* d_out, int out_size) {
    const float* q    = (const float*)d_in[0];
    const float* k    = (const float*)d_in[1];
    const float* v    = (const float*)d_in[2];
    const int*   mask = (const int*)d_in[3];

    float* out  = (float*)d_out;                          // [B,H,S,D]
    float* prob = out + (size_t)BB * HH * SS * DD;        // [B,H,S,S]

    pack_mask_kernel<<<(SS * SS) / NTH, NTH>>>(mask);
    split_kv_kernel<<<(KVELEM / 8) / NTH, NTH>>>(k, v);

    cudaFuncSetAttribute(sdpa_mma_kernel,
                         cudaFuncAttributeMaxDynamicSharedMemorySize, SMEM_TOTAL);
    dim3 grid(BB * HH * (SS / QT));   // 512 CTAs
    sdpa_mma_kernel<<<grid, NTH, SMEM_TOTAL>>>(q, out, prob);
}

// round 6
// speedup vs baseline: 6.6748x; 1.2610x over previous
#include <cuda_runtime.h>
#include <cuda_fp16.h>
#include <cstdint>

typedef uint32_t u32;

#define BB 2
#define HH 16
#define SS 2048
#define DD 64
#define QT 128
#define KT 128
#define NKB (SS/KT)
#define NTH 256
#define CEXP 0.18033688011112042f   // 0.125 * log2(e)
#define KVELEM (BB*HH*SS*DD)        // 4,194,304

// double-buffered smem: buf{0,1} each = KH(16K) + VH(16K)
#define OFF_VH 16384
#define BUFSZ  32768
#define SMEM_TOTAL 65536

__device__ u32   g_maskbits[SS * SS / 32];             // 512 KB
__device__ uint4 g_kh[KVELEM / 8], g_vh[KVELEM / 8];   // fp16 K,V (8 MB each)

__global__ void pack_mask_kernel(const int* __restrict__ mask) {
    int g = blockIdx.x * blockDim.x + threadIdx.x;
    u32 b = __ballot_sync(0xffffffffu, mask[g] != 0);
    if ((threadIdx.x & 31) == 0) g_maskbits[g >> 5] = b;
}

__device__ __forceinline__ float ex2f(float x) {
    float r; asm("ex2.approx.f32 %0, %1;" : "=f"(r) : "f"(x)); return r;
}
__device__ __forceinline__ u32 packh(float x, float y) {
    __half2 h = __floats2half2_rn(x, y);
    return *reinterpret_cast<u32*>(&h);
}
__device__ __forceinline__ u32 splith(float x, float y, u32& lo) {
    __half2 h = __floats2half2_rn(x, y);
    float2 hf = __half22float2(h);
    __half2 lw = __floats2half2_rn(x - hf.x, y - hf.y);
    lo = *reinterpret_cast<u32*>(&lw);
    return *reinterpret_cast<u32*>(&h);
}

__global__ void split_kv_kernel(const float* __restrict__ K, const float* __restrict__ V) {
    int i = blockIdx.x * blockDim.x + threadIdx.x;   // uint4 index (8 halves)
    const float4* k4 = (const float4*)K;
    const float4* v4 = (const float4*)V;
    float4 a = k4[2 * i], b = k4[2 * i + 1];
    g_kh[i] = make_uint4(packh(a.x, a.y), packh(a.z, a.w), packh(b.x, b.y), packh(b.z, b.w));
    a = v4[2 * i]; b = v4[2 * i + 1];
    g_vh[i] = make_uint4(packh(a.x, a.y), packh(a.z, a.w), packh(b.x, b.y), packh(b.z, b.w));
}

__device__ __forceinline__ void mma_f16(float c[4], const u32 a[4], u32 b0, u32 b1) {
    asm volatile("mma.sync.aligned.m16n8k16.row.col.f32.f16.f16.f32 "
        "{%0,%1,%2,%3}, {%4,%5,%6,%7}, {%8,%9}, {%0,%1,%2,%3};"
        : "+f"(c[0]), "+f"(c[1]), "+f"(c[2]), "+f"(c[3])
        : "r"(a[0]), "r"(a[1]), "r"(a[2]), "r"(a[3]), "r"(b0), "r"(b1));
}
__device__ __forceinline__ void ldsm4(u32& r0, u32& r1, u32& r2, u32& r3, u32 a) {
    asm volatile("ldmatrix.sync.aligned.m8n8.x4.shared.b16 {%0,%1,%2,%3}, [%4];"
        : "=r"(r0), "=r"(r1), "=r"(r2), "=r"(r3) : "r"(a));
}
__device__ __forceinline__ void ldsm4t(u32& r0, u32& r1, u32& r2, u32& r3, u32 a) {
    asm volatile("ldmatrix.sync.aligned.m8n8.x4.trans.shared.b16 {%0,%1,%2,%3}, [%4];"
        : "=r"(r0), "=r"(r1), "=r"(r2), "=r"(r3) : "r"(a));
}
__device__ __forceinline__ void cpa16(u32 dst, const void* src) {
    asm volatile("cp.async.cg.shared.global [%0], [%1], 16;" :: "r"(dst), "l"(src));
}
#define CP_COMMIT() asm volatile("cp.async.commit_group;" ::: "memory")
#define CP_WAIT1()  asm volatile("cp.async.wait_group 1;" ::: "memory")
#define CP_WAIT0()  asm volatile("cp.async.wait_group 0;" ::: "memory")

// XOR-swizzled dst offset for linear 16B chunk i of a [128 x 64h] tile
__device__ __forceinline__ u32 swz_dst(int i) {
    return (u32)(((i >> 3) << 7) + (((i & 7) ^ ((i >> 3) & 7)) << 4));
}

__global__ void __launch_bounds__(NTH, 2)
sdpa_mma_kernel(const float* __restrict__ Q,
                float* __restrict__ Out, float* __restrict__ Prob) {
    extern __shared__ char sm[];
    u32 sb;
    asm("{ .reg .u64 t; cvta.to.shared.u64 t, %1; cvt.u32.u64 %0, t; }" : "=r"(sb) : "l"(sm));

    const int t = threadIdx.x;
    const int w = t >> 5, l = t & 31;
    const int gr = l >> 2, c = l & 3;

    const int qblk = blockIdx.x >> 5;   // 0..15
    const int bh   = blockIdx.x & 31;   // 0..31
    const int q0   = qblk * QT;
    const int qw0  = w * 16;

    const size_t bhbase = (size_t)bh * (SS * DD / 8);
    const uint4* pkh = g_kh + bhbase;   // one kb tile = 1024 uint4 chunks
    const uint4* pvh = g_vh + bhbase;

    // ---- resident Q fragments (fp16 hi/lo) ----
    u32 qh[4][4], ql[4][4];
    {
        const float* Qp = Q + ((size_t)bh * SS + q0 + qw0) * DD;
        #pragma unroll
        for (int ks = 0; ks < 4; ks++) {
            const float* r0 = Qp + gr * DD + ks * 16 + 2 * c;
            const float* r1 = r0 + 8 * DD;
            float2 f00 = *(const float2*)(r0);
            float2 f10 = *(const float2*)(r1);
            float2 f01 = *(const float2*)(r0 + 8);
            float2 f11 = *(const float2*)(r1 + 8);
            qh[ks][0] = splith(f00.x, f00.y, ql[ks][0]);
            qh[ks][1] = splith(f10.x, f10.y, ql[ks][1]);
            qh[ks][2] = splith(f01.x, f01.y, ql[ks][2]);
            qh[ks][3] = splith(f11.x, f11.y, ql[ks][3]);
        }
    }

    const int mrow0 = q0 + qw0 + gr;
    const u32* mw0 = g_maskbits + (size_t)mrow0 * (SS / 32);
    const u32* mw1 = mw0 + 8 * (SS / 32);

    // ldmatrix lane constants
    const int rl  = ((l >> 4) & 1) * 8 + (l & 7);   // QK rows
    const int clk = (l >> 3) & 1;
    const u32 lkA = (u32)(rl << 7), lks = (u32)(rl & 7);
    const int rv  = ((l >> 3) & 1) * 8 + (l & 7);   // PV (trans) rows
    const int cv  = (l >> 4) & 1;
    const u32 lvA = (u32)(rv << 7), lvs = (u32)(rv & 7);

    float l0 = 0.f, l1 = 0.f;

    // =================== PASS 1: row sums (qh·kh only) ===================
    // double-buffered K fills
    #pragma unroll
    for (int j = 0; j < 4; j++) {
        int i = t + j * NTH;
        cpa16(sb + swz_dst(i), pkh + i);
    }
    CP_COMMIT();
    for (int kb = 0; kb < NKB; kb++) {
        const u32 bufA = sb + (u32)((kb & 1) * BUFSZ);
        const u32 bufB = sb + (u32)(((kb + 1) & 1) * BUFSZ);
        if (kb + 1 < NKB) {
            #pragma unroll
            for (int j = 0; j < 4; j++) {
                int i = t + j * NTH;
                cpa16(bufB + swz_dst(i), pkh + (size_t)(kb + 1) * 1024 + i);
            }
        }
        CP_COMMIT();
        CP_WAIT1();
        __syncthreads();

        #pragma unroll
        for (int jp = 0; jp < 8; jp++) {
            float s0[4] = {0.f, 0.f, 0.f, 0.f}, s1[4] = {0.f, 0.f, 0.f, 0.f};
            #pragma unroll
            for (int ks = 0; ks < 4; ks++) {
                u32 b0, b1, b2, b3;
                u32 a = bufA + (u32)(jp * 2048) + lkA + ((((u32)(ks << 1) | clk) ^ lks) << 4);
                ldsm4(b0, b1, b2, b3, a);
                mma_f16(s0, qh[ks], b0, b1);
                mma_f16(s1, qh[ks], b2, b3);
            }
            u32 w0 = mw0[kb * 4 + (jp >> 1)];
            u32 w1 = mw1[kb * 4 + (jp >> 1)];
            int sh = ((jp & 1) << 4) + 2 * c;
            l0 += (float)((w0 >> sh) & 1u)        * ex2f(s0[0] * CEXP);
            l0 += (float)((w0 >> (sh + 1)) & 1u)  * ex2f(s0[1] * CEXP);
            l1 += (float)((w1 >> sh) & 1u)        * ex2f(s0[2] * CEXP);
            l1 += (float)((w1 >> (sh + 1)) & 1u)  * ex2f(s0[3] * CEXP);
            l0 += (float)((w0 >> (sh + 8)) & 1u)  * ex2f(s1[0] * CEXP);
            l0 += (float)((w0 >> (sh + 9)) & 1u)  * ex2f(s1[1] * CEXP);
            l1 += (float)((w1 >> (sh + 8)) & 1u)  * ex2f(s1[2] * CEXP);
            l1 += (float)((w1 >> (sh + 9)) & 1u)  * ex2f(s1[3] * CEXP);
        }
        __syncthreads();
    }
    CP_WAIT0();
    l0 += __shfl_xor_sync(0xffffffffu, l0, 1);
    l0 += __shfl_xor_sync(0xffffffffu, l0, 2);
    l1 += __shfl_xor_sync(0xffffffffu, l1, 1);
    l1 += __shfl_xor_sync(0xffffffffu, l1, 2);
    const float inv0 = 1.f / l0, inv1 = 1.f / l1;
    __syncthreads();

    // =================== PASS 2: P write + O = P@V ===================
    float oacc[8][4];
    #pragma unroll
    for (int on = 0; on < 8; on++)
        #pragma unroll
        for (int x = 0; x < 4; x++) oacc[on][x] = 0.f;

    const size_t gq = (size_t)bh * SS + q0 + qw0;
    float* pr0base = Prob + (gq + gr) * SS + 2 * c;
    float* pr1base = pr0base + 8 * SS;

    #pragma unroll
    for (int j = 0; j < 4; j++) {
        int i = t + j * NTH;
        u32 d = swz_dst(i);
        cpa16(sb + d, pkh + i);
        cpa16(sb + OFF_VH + d, pvh + i);
    }
    CP_COMMIT();

    for (int kb = 0; kb < NKB; kb++) {
        const u32 bufA = sb + (u32)((kb & 1) * BUFSZ);
        const u32 bufB = sb + (u32)(((kb + 1) & 1) * BUFSZ);
        if (kb + 1 < NKB) {
            #pragma unroll
            for (int j = 0; j < 4; j++) {
                int i = t + j * NTH;
                const size_t gi = (size_t)(kb + 1) * 1024 + i;
                u32 d = swz_dst(i);
                cpa16(bufB + d, pkh + gi);
                cpa16(bufB + OFF_VH + d, pvh + gi);
            }
        }
        CP_COMMIT();
        CP_WAIT1();
        __syncthreads();

        float* p0 = pr0base + (size_t)kb * KT;
        float* p1 = pr1base + (size_t)kb * KT;

        #pragma unroll
        for (int jp = 0; jp < 8; jp++) {
            float s0[4] = {0.f, 0.f, 0.f, 0.f}, s1[4] = {0.f, 0.f, 0.f, 0.f};
            #pragma unroll
            for (int ks = 0; ks < 4; ks++) {
                u32 b0, b1, b2, b3;
                u32 off = bufA + (u32)(jp * 2048) + lkA + ((((u32)(ks << 1) | clk) ^ lks) << 4);
                ldsm4(b0, b1, b2, b3, off);
                mma_f16(s0, qh[ks], b0, b1);
                mma_f16(s0, ql[ks], b0, b1);
                mma_f16(s1, qh[ks], b2, b3);
                mma_f16(s1, ql[ks], b2, b3);
            }

            u32 w0 = mw0[kb * 4 + (jp >> 1)];
            u32 w1 = mw1[kb * 4 + (jp >> 1)];
            int sh = ((jp & 1) << 4) + 2 * c;

            u32 aH[4], aL[4];
            {
                float e00 = (float)((w0 >> sh) & 1u)       * ex2f(s0[0] * CEXP) * inv0;
                float e01 = (float)((w0 >> (sh + 1)) & 1u) * ex2f(s0[1] * CEXP) * inv0;
                float e10 = (float)((w1 >> sh) & 1u)       * ex2f(s0[2] * CEXP) * inv1;
                float e11 = (float)((w1 >> (sh + 1)) & 1u) * ex2f(s0[3] * CEXP) * inv1;
                __stcs((float2*)(p0 + (2 * jp) * 8), make_float2(e00, e01));
                __stcs((float2*)(p1 + (2 * jp) * 8), make_float2(e10, e11));
                aH[0] = splith(e00, e01, aL[0]);
                aH[1] = splith(e10, e11, aL[1]);
            }
            {
                float e00 = (float)((w0 >> (sh + 8)) & 1u) * ex2f(s1[0] * CEXP) * inv0;
                float e01 = (float)((w0 >> (sh + 9)) & 1u) * ex2f(s1[1] * CEXP) * inv0;
                float e10 = (float)((w1 >> (sh + 8)) & 1u) * ex2f(s1[2] * CEXP) * inv1;
                float e11 = (float)((w1 >> (sh + 9)) & 1u) * ex2f(s1[3] * CEXP) * inv1;
                __stcs((float2*)(p0 + (2 * jp + 1) * 8), make_float2(e00, e01));
                __stcs((float2*)(p1 + (2 * jp + 1) * 8), make_float2(e10, e11));
                aH[2] = splith(e00, e01, aL[2]);
                aH[3] = splith(e10, e11, aL[3]);
            }

            #pragma unroll
            for (int op = 0; op < 4; op++) {
                u32 v0, v1, v2, v3;
                u32 off = bufA + OFF_VH + (u32)(jp * 2048) + lvA
                        + ((((u32)(op << 1) | cv) ^ lvs) << 4);
                ldsm4t(v0, v1, v2, v3, off);
                mma_f16(oacc[2 * op],     aH, v0, v1);
                mma_f16(oacc[2 * op],     aL, v0, v1);
                mma_f16(oacc[2 * op + 1], aH, v2, v3);
                mma_f16(oacc[2 * op + 1], aL, v2, v3);
            }
        }
        __syncthreads();
    }

    // ---- O writeout ----
    {
        float* o0 = Out + (gq + gr) * DD + 2 * c;
        float* o1 = o0 + 8 * DD;
        #pragma unroll
        for (int on = 0; on < 8; on++) {
            *(float2*)(o0 + on * 8) = make_float2(oacc[on][0], oacc[on][1]);
            *(float2*)(o1 + on * 8) = make_float2(oacc[on][2], oacc[on][3]);
        }
    }
}

extern "C" void kernel_launch(void* const* d_in, const int* in_sizes, int n_in,
                              void* d_out, int out_size) {
    const float* q    = (const float*)d_in[0];
    const float* k    = (const float*)d_in[1];
    const float* v    = (const float*)d_in[2];
    const int*   mask = (const int*)d_in[3];

    float* out  = (float*)d_out;                          // [B,H,S,D]
    float* prob = out + (size_t)BB * HH * SS * DD;        // [B,H,S,S]

    pack_mask_kernel<<<(SS * SS) / NTH, NTH>>>(mask);
    split_kv_kernel<<<(KVELEM / 8) / NTH, NTH>>>(k, v);

    cudaFuncSetAttribute(sdpa_mma_kernel,
                         cudaFuncAttributeMaxDynamicSharedMemorySize, SMEM_TOTAL);
    dim3 grid(BB * HH * (SS / QT));   // 512 CTAs
    sdpa_mma_kernel<<<grid, NTH, SMEM_TOTAL>>>(q, out, prob);
}

// round 7
// speedup vs baseline: 7.6543x; 1.1468x over previous
#include <cuda_runtime.h>
#include <cuda_fp16.h>
#include <cstdint>

typedef uint32_t u32;

#define BB 2
#define HH 16
#define SS 2048
#define DD 64
#define QT 128
#define KT 128
#define NKB (SS/KT)
#define NTH 256
#define CEXP 0.18033688011112042f   // 0.125 * log2(e)
#define MASKED_ARG (-1.0e4f)        // ex2.ftz -> exactly 0
#define KVELEM (BB*HH*SS*DD)        // 4,194,304

// double-buffered smem: buf{0,1} each = KH(16K) + VH(16K)
#define OFF_VH 16384
#define BUFSZ  32768
#define SMEM_TOTAL 65536

__device__ u32   g_maskbits[SS * SS / 32];             // 512 KB
__device__ uint4 g_kh[KVELEM / 8], g_vh[KVELEM / 8];   // fp16 K,V (8 MB each)

__global__ void pack_mask_kernel(const int* __restrict__ mask) {
    int g = blockIdx.x * blockDim.x + threadIdx.x;
    u32 b = __ballot_sync(0xffffffffu, mask[g] != 0);
    if ((threadIdx.x & 31) == 0) g_maskbits[g >> 5] = b;
}

__device__ __forceinline__ float ex2f(float x) {
    float r; asm("ex2.approx.ftz.f32 %0, %1;" : "=f"(r) : "f"(x)); return r;
}
__device__ __forceinline__ float lg2f(float x) {
    float r; asm("lg2.approx.f32 %0, %1;" : "=f"(r) : "f"(x)); return r;
}
__device__ __forceinline__ u32 packh(float x, float y) {
    __half2 h = __floats2half2_rn(x, y);
    return *reinterpret_cast<u32*>(&h);
}
__device__ __forceinline__ u32 splith(float x, float y, u32& lo) {
    __half2 h = __floats2half2_rn(x, y);
    float2 hf = __half22float2(h);
    __half2 lw = __floats2half2_rn(x - hf.x, y - hf.y);
    lo = *reinterpret_cast<u32*>(&lw);
    return *reinterpret_cast<u32*>(&h);
}

__global__ void split_kv_kernel(const float* __restrict__ K, const float* __restrict__ V) {
    int i = blockIdx.x * blockDim.x + threadIdx.x;   // uint4 index (8 halves)
    const float4* k4 = (const float4*)K;
    const float4* v4 = (const float4*)V;
    float4 a = k4[2 * i], b = k4[2 * i + 1];
    g_kh[i] = make_uint4(packh(a.x, a.y), packh(a.z, a.w), packh(b.x, b.y), packh(b.z, b.w));
    a = v4[2 * i]; b = v4[2 * i + 1];
    g_vh[i] = make_uint4(packh(a.x, a.y), packh(a.z, a.w), packh(b.x, b.y), packh(b.z, b.w));
}

__device__ __forceinline__ void mma_f16(float c[4], const u32 a[4], u32 b0, u32 b1) {
    asm volatile("mma.sync.aligned.m16n8k16.row.col.f32.f16.f16.f32 "
        "{%0,%1,%2,%3}, {%4,%5,%6,%7}, {%8,%9}, {%0,%1,%2,%3};"
        : "+f"(c[0]), "+f"(c[1]), "+f"(c[2]), "+f"(c[3])
        : "r"(a[0]), "r"(a[1]), "r"(a[2]), "r"(a[3]), "r"(b0), "r"(b1));
}
__device__ __forceinline__ void ldsm4(u32& r0, u32& r1, u32& r2, u32& r3, u32 a) {
    asm volatile("ldmatrix.sync.aligned.m8n8.x4.shared.b16 {%0,%1,%2,%3}, [%4];"
        : "=r"(r0), "=r"(r1), "=r"(r2), "=r"(r3) : "r"(a));
}
__device__ __forceinline__ void ldsm4t(u32& r0, u32& r1, u32& r2, u32& r3, u32 a) {
    asm volatile("ldmatrix.sync.aligned.m8n8.x4.trans.shared.b16 {%0,%1,%2,%3}, [%4];"
        : "=r"(r0), "=r"(r1), "=r"(r2), "=r"(r3) : "r"(a));
}
__device__ __forceinline__ void cpa16(u32 dst, const void* src) {
    asm volatile("cp.async.cg.shared.global [%0], [%1], 16;" :: "r"(dst), "l"(src));
}
#define CP_COMMIT() asm volatile("cp.async.commit_group;" ::: "memory")
#define CP_WAIT1()  asm volatile("cp.async.wait_group 1;" ::: "memory")
#define CP_WAIT0()  asm volatile("cp.async.wait_group 0;" ::: "memory")

// XOR-swizzled dst offset for linear 16B chunk i of a [128 x 64h] tile
__device__ __forceinline__ u32 swz_dst(int i) {
    return (u32)(((i >> 3) << 7) + (((i & 7) ^ ((i >> 3) & 7)) << 4));
}

__global__ void __launch_bounds__(NTH, 2)
sdpa_mma_kernel(const float* __restrict__ Q,
                float* __restrict__ Out, float* __restrict__ Prob) {
    extern __shared__ char sm[];
    u32 sb;
    asm("{ .reg .u64 t; cvta.to.shared.u64 t, %1; cvt.u32.u64 %0, t; }" : "=r"(sb) : "l"(sm));

    const int t = threadIdx.x;
    const int w = t >> 5, l = t & 31;
    const int gr = l >> 2, c = l & 3;

    const int qblk = blockIdx.x >> 5;   // 0..15
    const int bh   = blockIdx.x & 31;   // 0..31
    const int q0   = qblk * QT;
    const int qw0  = w * 16;

    const size_t bhbase = (size_t)bh * (SS * DD / 8);
    const uint4* pkh = g_kh + bhbase;   // one kb tile = 1024 uint4 chunks
    const uint4* pvh = g_vh + bhbase;

    // ---- resident Q fragments (fp16 hi/lo) ----
    u32 qh[4][4], ql[4][4];
    {
        const float* Qp = Q + ((size_t)bh * SS + q0 + qw0) * DD;
        #pragma unroll
        for (int ks = 0; ks < 4; ks++) {
            const float* r0 = Qp + gr * DD + ks * 16 + 2 * c;
            const float* r1 = r0 + 8 * DD;
            float2 f00 = *(const float2*)(r0);
            float2 f10 = *(const float2*)(r1);
            float2 f01 = *(const float2*)(r0 + 8);
            float2 f11 = *(const float2*)(r1 + 8);
            qh[ks][0] = splith(f00.x, f00.y, ql[ks][0]);
            qh[ks][1] = splith(f10.x, f10.y, ql[ks][1]);
            qh[ks][2] = splith(f01.x, f01.y, ql[ks][2]);
            qh[ks][3] = splith(f11.x, f11.y, ql[ks][3]);
        }
    }

    const int mrow0 = q0 + qw0 + gr;
    const u32* mw0 = g_maskbits + (size_t)mrow0 * (SS / 32);
    const u32* mw1 = mw0 + 8 * (SS / 32);

    // hoisted mask bit tests (within a 16-bit half-word)
    const u32 bm0 = 1u << (2 * c), bm1 = 2u << (2 * c);
    const u32 bm8 = bm0 << 8,      bm9 = bm1 << 8;

    // ldmatrix lane constants
    const int rl  = ((l >> 4) & 1) * 8 + (l & 7);   // QK rows
    const int clk = (l >> 3) & 1;
    const u32 lkA = (u32)(rl << 7), lks = (u32)(rl & 7);
    const int rv  = ((l >> 3) & 1) * 8 + (l & 7);   // PV (trans) rows
    const int cv  = (l >> 4) & 1;
    const u32 lvA = (u32)(rv << 7), lvs = (u32)(rv & 7);

    float l0 = 0.f, l1 = 0.f;

    // =================== PASS 1: row sums (qh·kh only) ===================
    #pragma unroll
    for (int j = 0; j < 4; j++) {
        int i = t + j * NTH;
        cpa16(sb + swz_dst(i), pkh + i);
    }
    CP_COMMIT();
    for (int kb = 0; kb < NKB; kb++) {
        const u32 bufA = sb + (u32)((kb & 1) * BUFSZ);
        const u32 bufB = sb + (u32)(((kb + 1) & 1) * BUFSZ);
        if (kb + 1 < NKB) {
            #pragma unroll
            for (int j = 0; j < 4; j++) {
                int i = t + j * NTH;
                cpa16(bufB + swz_dst(i), pkh + (size_t)(kb + 1) * 1024 + i);
            }
        }
        CP_COMMIT();
        CP_WAIT1();
        __syncthreads();

        #pragma unroll
        for (int jp = 0; jp < 8; jp++) {
            float s0[4] = {0.f, 0.f, 0.f, 0.f}, s1[4] = {0.f, 0.f, 0.f, 0.f};
            #pragma unroll
            for (int ks = 0; ks < 4; ks++) {
                u32 b0, b1, b2, b3;
                u32 a = bufA + (u32)(jp * 2048) + lkA + ((((u32)(ks << 1) | clk) ^ lks) << 4);
                ldsm4(b0, b1, b2, b3, a);
                mma_f16(s0, qh[ks], b0, b1);
                mma_f16(s1, qh[ks], b2, b3);
            }
            u32 w0 = mw0[kb * 4 + (jp >> 1)];
            u32 w1 = mw1[kb * 4 + (jp >> 1)];
            u32 W0 = (jp & 1) ? (w0 >> 16) : w0;
            u32 W1 = (jp & 1) ? (w1 >> 16) : w1;
            float a0 = (W0 & bm0) ? s0[0] * CEXP : MASKED_ARG;
            float a1 = (W0 & bm1) ? s0[1] * CEXP : MASKED_ARG;
            float a2 = (W1 & bm0) ? s0[2] * CEXP : MASKED_ARG;
            float a3 = (W1 & bm1) ? s0[3] * CEXP : MASKED_ARG;
            float a4 = (W0 & bm8) ? s1[0] * CEXP : MASKED_ARG;
            float a5 = (W0 & bm9) ? s1[1] * CEXP : MASKED_ARG;
            float a6 = (W1 & bm8) ? s1[2] * CEXP : MASKED_ARG;
            float a7 = (W1 & bm9) ? s1[3] * CEXP : MASKED_ARG;
            l0 += ex2f(a0) + ex2f(a1);
            l1 += ex2f(a2) + ex2f(a3);
            l0 += ex2f(a4) + ex2f(a5);
            l1 += ex2f(a6) + ex2f(a7);
        }
        __syncthreads();
    }
    CP_WAIT0();
    l0 += __shfl_xor_sync(0xffffffffu, l0, 1);
    l0 += __shfl_xor_sync(0xffffffffu, l0, 2);
    l1 += __shfl_xor_sync(0xffffffffu, l1, 1);
    l1 += __shfl_xor_sync(0xffffffffu, l1, 2);
    const float linv0 = -lg2f(l0);     // fold 1/l into the exponent
    const float linv1 = -lg2f(l1);
    __syncthreads();

    // =================== PASS 2: P write + O = P@V ===================
    float oacc[8][4];
    #pragma unroll
    for (int on = 0; on < 8; on++)
        #pragma unroll
        for (int x = 0; x < 4; x++) oacc[on][x] = 0.f;

    const size_t gq = (size_t)bh * SS + q0 + qw0;
    float* pr0base = Prob + (gq + gr) * SS + 2 * c;
    float* pr1base = pr0base + 8 * SS;

    #pragma unroll
    for (int j = 0; j < 4; j++) {
        int i = t + j * NTH;
        u32 d = swz_dst(i);
        cpa16(sb + d, pkh + i);
        cpa16(sb + OFF_VH + d, pvh + i);
    }
    CP_COMMIT();

    for (int kb = 0; kb < NKB; kb++) {
        const u32 bufA = sb + (u32)((kb & 1) * BUFSZ);
        const u32 bufB = sb + (u32)(((kb + 1) & 1) * BUFSZ);
        if (kb + 1 < NKB) {
            #pragma unroll
            for (int j = 0; j < 4; j++) {
                int i = t + j * NTH;
                const size_t gi = (size_t)(kb + 1) * 1024 + i;
                u32 d = swz_dst(i);
                cpa16(bufB + d, pkh + gi);
                cpa16(bufB + OFF_VH + d, pvh + gi);
            }
        }
        CP_COMMIT();
        CP_WAIT1();
        __syncthreads();

        float* p0 = pr0base + (size_t)kb * KT;
        float* p1 = pr1base + (size_t)kb * KT;

        #pragma unroll
        for (int jp = 0; jp < 8; jp++) {
            float s0[4] = {0.f, 0.f, 0.f, 0.f}, s1[4] = {0.f, 0.f, 0.f, 0.f};
            #pragma unroll
            for (int ks = 0; ks < 4; ks++) {
                u32 b0, b1, b2, b3;
                u32 off = bufA + (u32)(jp * 2048) + lkA + ((((u32)(ks << 1) | clk) ^ lks) << 4);
                ldsm4(b0, b1, b2, b3, off);
                mma_f16(s0, qh[ks], b0, b1);
                mma_f16(s0, ql[ks], b0, b1);
                mma_f16(s1, qh[ks], b2, b3);
                mma_f16(s1, ql[ks], b2, b3);
            }

            u32 w0 = mw0[kb * 4 + (jp >> 1)];
            u32 w1 = mw1[kb * 4 + (jp >> 1)];
            u32 W0 = (jp & 1) ? (w0 >> 16) : w0;
            u32 W1 = (jp & 1) ? (w1 >> 16) : w1;

            u32 aH[4];
            {
                float a0 = (W0 & bm0) ? fmaf(s0[0], CEXP, linv0) : MASKED_ARG;
                float a1 = (W0 & bm1) ? fmaf(s0[1], CEXP, linv0) : MASKED_ARG;
                float a2 = (W1 & bm0) ? fmaf(s0[2], CEXP, linv1) : MASKED_ARG;
                float a3 = (W1 & bm1) ? fmaf(s0[3], CEXP, linv1) : MASKED_ARG;
                float e00 = ex2f(a0), e01 = ex2f(a1);
                float e10 = ex2f(a2), e11 = ex2f(a3);
                __stcs((float2*)(p0 + (2 * jp) * 8), make_float2(e00, e01));
                __stcs((float2*)(p1 + (2 * jp) * 8), make_float2(e10, e11));
                aH[0] = packh(e00, e01);
                aH[1] = packh(e10, e11);
            }
            {
                float a0 = (W0 & bm8) ? fmaf(s1[0], CEXP, linv0) : MASKED_ARG;
                float a1 = (W0 & bm9) ? fmaf(s1[1], CEXP, linv0) : MASKED_ARG;
                float a2 = (W1 & bm8) ? fmaf(s1[2], CEXP, linv1) : MASKED_ARG;
                float a3 = (W1 & bm9) ? fmaf(s1[3], CEXP, linv1) : MASKED_ARG;
                float e00 = ex2f(a0), e01 = ex2f(a1);
                float e10 = ex2f(a2), e11 = ex2f(a3);
                __stcs((float2*)(p0 + (2 * jp + 1) * 8), make_float2(e00, e01));
                __stcs((float2*)(p1 + (2 * jp + 1) * 8), make_float2(e10, e11));
                aH[2] = packh(e00, e01);
                aH[3] = packh(e10, e11);
            }

            #pragma unroll
            for (int op = 0; op < 4; op++) {
                u32 v0, v1, v2, v3;
                u32 off = bufA + OFF_VH + (u32)(jp * 2048) + lvA
                        + ((((u32)(op << 1) | cv) ^ lvs) << 4);
                ldsm4t(v0, v1, v2, v3, off);
                mma_f16(oacc[2 * op],     aH, v0, v1);
                mma_f16(oacc[2 * op + 1], aH, v2, v3);
            }
        }
        __syncthreads();
    }

    // ---- O writeout ----
    {
        float* o0 = Out + (gq + gr) * DD + 2 * c;
        float* o1 = o0 + 8 * DD;
        #pragma unroll
        for (int on = 0; on < 8; on++) {
            *(float2*)(o0 + on * 8) = make_float2(oacc[on][0], oacc[on][1]);
            *(float2*)(o1 + on * 8) = make_float2(oacc[on][2], oacc[on][3]);
        }
    }
}

extern "C" void kernel_launch(void* const* d_in, const int* in_sizes, int n_in,
                              void* d_out, int out_size) {
    const float* q    = (const float*)d_in[0];
    const float* k    = (const float*)d_in[1];
    const float* v    = (const float*)d_in[2];
    const int*   mask = (const int*)d_in[3];

    float* out  = (float*)d_out;                          // [B,H,S,D]
    float* prob = out + (size_t)BB * HH * SS * DD;        // [B,H,S,S]

    pack_mask_kernel<<<(SS * SS) / NTH, NTH>>>(mask);
    split_kv_kernel<<<(KVELEM / 8) / NTH, NTH>>>(k, v);

    cudaFuncSetAttribute(sdpa_mma_kernel,
                         cudaFuncAttributeMaxDynamicSharedMemorySize, SMEM_TOTAL);
    dim3 grid(BB * HH * (SS / QT));   // 512 CTAs
    sdpa_mma_kernel<<<grid, NTH, SMEM_TOTAL>>>(q, out, prob);
}